// round 14
// baseline (speedup 1.0000x reference)
#include <cuda_runtime.h>
#include <cuda_fp16.h>
#include <math.h>
#include <stdint.h>

#define NB   32
#define NC   512
#define NHW  1024
#define CHW  (NC * NHW)

// ---------------- persistent scratch (fp16 operands) ----------------
__device__ __half g_qkv[(size_t)NB * 3 * CHW];      // Q | K | V  [b][1536][1024]
__device__ __half g_hin[(size_t)NB * CHW];          // gn(x) [b][c][p]
__device__ __half g_P [(size_t)NB * NHW * NHW];     // post-softmax [b][p][q]
__device__ __half g_H [(size_t)NB * CHW];           // [b][c][p]
__device__ __half g_wq[1536 * NC];
__device__ __half g_wp[NC * NC];

// ---------------- PTX helpers (baseline sm_80-era ISA only) ----------------
__device__ __forceinline__ uint32_t smem_u32(const void* p) {
    uint32_t a;
    asm("{ .reg .u64 t; cvta.to.shared.u64 t, %1; cvt.u32.u64 %0, t; }" : "=r"(a) : "l"(p));
    return a;
}
#define LDSM4(R, a) \
    asm volatile("ldmatrix.sync.aligned.m8n8.x4.shared.b16 {%0,%1,%2,%3}, [%4];" \
        : "=r"((R)[0]), "=r"((R)[1]), "=r"((R)[2]), "=r"((R)[3]) : "r"(a))
#define LDSM4T(R, a) \
    asm volatile("ldmatrix.sync.aligned.m8n8.x4.trans.shared.b16 {%0,%1,%2,%3}, [%4];" \
        : "=r"((R)[0]), "=r"((R)[1]), "=r"((R)[2]), "=r"((R)[3]) : "r"(a))
#define CP16(d, s) \
    asm volatile("cp.async.cg.shared.global [%0], [%1], 16;" :: "r"(d), "l"(s))
#define CP_COMMIT() asm volatile("cp.async.commit_group;" ::: "memory")
#define CP_WAIT2()  asm volatile("cp.async.wait_group 2;" ::: "memory")
#define CP_WAIT1()  asm volatile("cp.async.wait_group 1;" ::: "memory")
#define CP_WAIT0()  asm volatile("cp.async.wait_group 0;" ::: "memory")

__device__ __forceinline__ void mma16816(float* d, const uint32_t* a, uint32_t b0, uint32_t b1) {
    asm volatile("mma.sync.aligned.m16n8k16.row.col.f32.f16.f16.f32 "
                 "{%0,%1,%2,%3}, {%4,%5,%6,%7}, {%8,%9}, {%0,%1,%2,%3};"
                 : "+f"(d[0]), "+f"(d[1]), "+f"(d[2]), "+f"(d[3])
                 : "r"(a[0]), "r"(a[1]), "r"(a[2]), "r"(a[3]), "r"(b0), "r"(b1));
}

__device__ __forceinline__ void store_h(__half* H, long long off, float2 v) {
    *reinterpret_cast<__half2*>(H + off) = __float22half2_rn(v);
}

// smem: 4 stages x (A | B), swizzled fp16 tiles (identical layout to R12)
//   direct tile: 128 rows x 64B (32 k-values), chunk(16B) swizzle: c ^= (row>>1)&3
//   trans  tile:  32 rows x 256B (128 mn-values), chunk(16B) swizzle: c ^= row&7
#define SLOT   8192
#define STAGEB 16384
#define SMEMB  65536

// 256 threads, 8 warps in 2x4 grid, warp tile 64x32, CTA tile 128x128.
// EPI: 0=QKV(+bias), 1=S(alpha + fused 32-wide softmax), 2=H, 3=proj(+bias+residual, fp32)
template<int EPI, bool TA, bool TB>
__global__ __launch_bounds__(256, 2)
void tc_gemm(const __half* __restrict__ A_, long long sAb, int lda,
             const __half* __restrict__ B_, long long sBb, int ldb,
             int Ktot,
             float* __restrict__ Cf, __half* __restrict__ Ch, long long sCb,
             const float* __restrict__ bias, const float* __restrict__ res, float alpha)
{
    extern __shared__ char sm[];
    const int tid = threadIdx.x, l = tid & 31, wid = tid >> 5;
    const int bz = blockIdx.z;
    const int m0 = blockIdx.y * 128, n0 = blockIdx.x * 128;
    const int wm = (wid >> 2) * 64, wn = (wid & 3) * 32;

    const __half* Ag = A_ + bz * sAb + (TA ? (long long)m0 : (long long)m0 * lda);
    const __half* Bg = B_ + bz * sBb + (TB ? (long long)n0 : (long long)n0 * ldb);

    const uint32_t smb = smem_u32(sm);

    // ---- hoisted cp.async addressing (per-thread; 2 chunks each for A and B) ----
    uint32_t aSts0, bSts0;
    {
        if (TA) {
            uint32_t r0 = (uint32_t)tid >> 4, ch = (uint32_t)tid & 15;
            aSts0 = r0 * 256 + ((ch ^ (r0 & 7)) << 4);
        } else {
            uint32_t r0 = (uint32_t)tid >> 2, ch = (uint32_t)tid & 3;
            aSts0 = r0 * 64 + ((ch ^ ((r0 >> 1) & 3)) << 4);
        }
        if (TB) {
            uint32_t r0 = (uint32_t)tid >> 4, ch = (uint32_t)tid & 15;
            bSts0 = r0 * 256 + ((ch ^ (r0 & 7)) << 4);
        } else {
            uint32_t r0 = (uint32_t)tid >> 2, ch = (uint32_t)tid & 3;
            bSts0 = r0 * 64 + ((ch ^ ((r0 >> 1) & 3)) << 4);
        }
    }
    const long long aGI  = TA ? 16LL * lda : 64LL * lda;  // per-i global step (i=0,1)
    const long long bGI  = TB ? 16LL * ldb : 64LL * ldb;
    const long long aAdv = TA ? 32LL * lda : 32LL;        // per-stage advance
    const long long bAdv = TB ? 32LL * ldb : 32LL;
    const __half* Ap = Ag + (TA ? ((long long)((uint32_t)tid >> 4)) * lda + ((tid & 15) * 8)
                                : ((long long)((uint32_t)tid >> 2)) * lda + ((tid & 3) * 8));
    const __half* Bp = Bg + (TB ? ((long long)((uint32_t)tid >> 4)) * ldb + ((tid & 15) * 8)
                                : ((long long)((uint32_t)tid >> 2)) * ldb + ((tid & 3) * 8));

    // ---- hoisted ldmatrix fragment addresses ----
    const uint32_t rdir = (uint32_t)(l & 15);
    const uint32_t dirLane = rdir * 64 + (((((rdir >> 1) & 3)) ^ (uint32_t)(l >> 4)) << 4);
    const uint32_t rr = (uint32_t)((l & 7) + ((l >> 4) << 3));
    const uint32_t g8 = (uint32_t)((l >> 3) & 1);
    const uint32_t trLane = rr * 256 + ((((uint32_t)(l & 7)) ^ g8) << 4);
    const uint32_t aLane = TA ? (trLane ^ (uint32_t)(wm * 2)) : (dirLane + wm * 64);
    const uint32_t bLane = TB ? (trLane ^ (uint32_t)(wn * 2)) : (dirLane + wn * 64);

    uint32_t adA[2][4], adB[2][2];
    #pragma unroll
    for (int h = 0; h < 2; h++) {
        #pragma unroll
        for (int mt = 0; mt < 4; mt++) {
            uint32_t a0;
            if (TA) { a0 = aLane + h * 4096u; a0 ^= (uint32_t)(mt << 5); }
            else    { a0 = aLane + mt * 1024u; a0 ^= (uint32_t)(h << 5); }
            adA[h][mt] = smb + a0;
        }
        #pragma unroll
        for (int g = 0; g < 2; g++) {
            uint32_t b0;
            if (TB) { b0 = bLane + h * 4096u; b0 ^= (uint32_t)(g << 5); }
            else    { b0 = bLane + g * 1024u; b0 ^= (uint32_t)(h << 5); }
            adB[h][g] = smb + SLOT + b0;
        }
    }

    float acc[4][4][4];
    #pragma unroll
    for (int i = 0; i < 4; i++)
        #pragma unroll
        for (int j = 0; j < 4; j++)
            #pragma unroll
            for (int k = 0; k < 4; k++) acc[i][j][k] = 0.f;

    auto ISSUE = [&](uint32_t buf) {
        uint32_t st = smb + buf * STAGEB;
        #pragma unroll
        for (int i = 0; i < 2; i++)
            CP16(st + aSts0 + i * 4096, Ap + i * aGI);
        #pragma unroll
        for (int i = 0; i < 2; i++)
            CP16(st + SLOT + bSts0 + i * 4096, Bp + i * bGI);
        Ap += aAdv; Bp += bAdv;
    };

    auto COMPUTE = [&](uint32_t buf) {
        const uint32_t bo = buf * STAGEB;
        #pragma unroll
        for (int h = 0; h < 2; h++) {
            uint32_t BF[2][4];
            #pragma unroll
            for (int g = 0; g < 2; g++) {
                if (TB) { LDSM4T(BF[g], adB[h][g] + bo); }
                else    { LDSM4 (BF[g], adB[h][g] + bo); }
            }
            #pragma unroll
            for (int mt = 0; mt < 4; mt++) {
                uint32_t AF[4];
                if (TA) { LDSM4T(AF, adA[h][mt] + bo); }
                else    { LDSM4 (AF, adA[h][mt] + bo); }
                #pragma unroll
                for (int nt = 0; nt < 4; nt++)
                    mma16816(acc[mt][nt], AF, BF[nt >> 1][nt & 1], BF[nt >> 1][2 + (nt & 1)]);
            }
        }
    };

    // ---- 4-stage cp.async pipeline, unrolled x4 (NS is 16 or 32) ----
    const int NS = Ktot / 32;
    ISSUE(0); CP_COMMIT();
    ISSUE(1); CP_COMMIT();
    ISSUE(2); CP_COMMIT();
    for (int s = 0; s < NS; s += 4) {
        #pragma unroll
        for (int j = 0; j < 4; j++) {
            int ss = s + j;
            int rem = NS - 1 - ss;
            if (rem >= 2)      { CP_WAIT2(); }
            else if (rem == 1) { CP_WAIT1(); }
            else               { CP_WAIT0(); }
            __syncthreads();
            if (ss + 3 < NS) { ISSUE((uint32_t)((j + 3) & 3)); CP_COMMIT(); }
            COMPUTE((uint32_t)j);
        }
    }

    // ---- epilogue ----
    if (EPI == 1) {
        __half* ChB = Ch + (long long)bz * sCb;
        #pragma unroll
        for (int mt = 0; mt < 4; mt++) {
            int r0 = m0 + wm + mt * 16 + (l >> 2);
            int r1 = r0 + 8;
            float vl[8], vh[8];
            #pragma unroll
            for (int nt = 0; nt < 4; nt++) {
                vl[2 * nt]     = acc[mt][nt][0] * alpha;
                vl[2 * nt + 1] = acc[mt][nt][1] * alpha;
                vh[2 * nt]     = acc[mt][nt][2] * alpha;
                vh[2 * nt + 1] = acc[mt][nt][3] * alpha;
            }
            float m_lo = vl[0], m_hi = vh[0];
            #pragma unroll
            for (int j = 1; j < 8; j++) { m_lo = fmaxf(m_lo, vl[j]); m_hi = fmaxf(m_hi, vh[j]); }
            m_lo = fmaxf(m_lo, __shfl_xor_sync(0xffffffffu, m_lo, 1));
            m_lo = fmaxf(m_lo, __shfl_xor_sync(0xffffffffu, m_lo, 2));
            m_hi = fmaxf(m_hi, __shfl_xor_sync(0xffffffffu, m_hi, 1));
            m_hi = fmaxf(m_hi, __shfl_xor_sync(0xffffffffu, m_hi, 2));
            float s_lo = 0.f, s_hi = 0.f;
            #pragma unroll
            for (int j = 0; j < 8; j++) {
                vl[j] = __expf(vl[j] - m_lo); s_lo += vl[j];
                vh[j] = __expf(vh[j] - m_hi); s_hi += vh[j];
            }
            s_lo += __shfl_xor_sync(0xffffffffu, s_lo, 1);
            s_lo += __shfl_xor_sync(0xffffffffu, s_lo, 2);
            s_hi += __shfl_xor_sync(0xffffffffu, s_hi, 1);
            s_hi += __shfl_xor_sync(0xffffffffu, s_hi, 2);
            float i_lo = 1.0f / s_lo, i_hi = 1.0f / s_hi;
            #pragma unroll
            for (int nt = 0; nt < 4; nt++) {
                int n = n0 + wn + nt * 8 + (l & 3) * 2;
                store_h(ChB, (long long)r0 * NHW + n,
                        make_float2(vl[2 * nt] * i_lo, vl[2 * nt + 1] * i_lo));
                store_h(ChB, (long long)r1 * NHW + n,
                        make_float2(vh[2 * nt] * i_hi, vh[2 * nt + 1] * i_hi));
            }
        }
    } else if (EPI == 3) {
        float* Cb = Cf + (long long)bz * sCb;
        const float* Rb = res + (long long)bz * sCb;
        #pragma unroll
        for (int mt = 0; mt < 4; mt++) {
            int r0 = m0 + wm + mt * 16 + (l >> 2);
            int r1 = r0 + 8;
            float b0v = bias[r0], b1v = bias[r1];
            #pragma unroll
            for (int nt = 0; nt < 4; nt++) {
                int n = n0 + wn + nt * 8 + (l & 3) * 2;
                float2 q0 = *(const float2*)(Rb + (long long)r0 * NHW + n);
                float2 q1 = *(const float2*)(Rb + (long long)r1 * NHW + n);
                *(float2*)(Cb + (long long)r0 * NHW + n) =
                    make_float2(acc[mt][nt][0] + b0v + q0.x, acc[mt][nt][1] + b0v + q0.y);
                *(float2*)(Cb + (long long)r1 * NHW + n) =
                    make_float2(acc[mt][nt][2] + b1v + q1.x, acc[mt][nt][3] + b1v + q1.y);
            }
        }
    } else {
        __half* ChB = Ch + (long long)bz * sCb;
        #pragma unroll
        for (int mt = 0; mt < 4; mt++) {
            int r0 = m0 + wm + mt * 16 + (l >> 2);
            int r1 = r0 + 8;
            float b0v = 0.f, b1v = 0.f;
            if (EPI == 0) { b0v = bias[r0]; b1v = bias[r1]; }
            #pragma unroll
            for (int nt = 0; nt < 4; nt++) {
                int n = n0 + wn + nt * 8 + (l & 3) * 2;
                store_h(ChB, (long long)r0 * NHW + n,
                        make_float2(acc[mt][nt][0] + b0v, acc[mt][nt][1] + b0v));
                store_h(ChB, (long long)r1 * NHW + n,
                        make_float2(acc[mt][nt][2] + b1v, acc[mt][nt][3] + b1v));
            }
        }
    }
}

// ---------------- fused GroupNorm: stats + normalize + fp16 ----------------
__global__ __launch_bounds__(256) void gn_all(
    const float* __restrict__ x, const float* __restrict__ gamma,
    const float* __restrict__ beta, __half* __restrict__ y)
{
    __shared__ float sred[16];
    int b = blockIdx.x >> 5, g = blockIdx.x & 31;
    const size_t gbase = (size_t)b * CHW + (size_t)g * 16 * NHW;
    const float4* xp = reinterpret_cast<const float4*>(x + gbase);
    const int N4 = 16 * NHW / 4;   // 4096
    float s = 0.f, s2 = 0.f;
    for (int i = threadIdx.x; i < N4; i += 256) {
        float4 v = xp[i];
        s  += v.x + v.y + v.z + v.w;
        s2 += v.x * v.x + v.y * v.y + v.z * v.z + v.w * v.w;
    }
    #pragma unroll
    for (int o = 16; o > 0; o >>= 1) {
        s  += __shfl_xor_sync(0xffffffffu, s,  o);
        s2 += __shfl_xor_sync(0xffffffffu, s2, o);
    }
    int warp = threadIdx.x >> 5, lane = threadIdx.x & 31;
    if (lane == 0) { sred[warp] = s; sred[8 + warp] = s2; }
    __syncthreads();
    if (threadIdx.x == 0) {
        float ts = 0.f, ts2 = 0.f;
        #pragma unroll
        for (int wi = 0; wi < 8; wi++) { ts += sred[wi]; ts2 += sred[8 + wi]; }
        const float invn = 1.0f / (16 * NHW);
        float mean = ts * invn;
        float var  = ts2 * invn - mean * mean;
        sred[0] = mean;
        sred[1] = rsqrtf(var + 1e-5f);
    }
    __syncthreads();
    float mean = sred[0], rstd = sred[1];

    __half2* py = reinterpret_cast<__half2*>(y + gbase);
    for (int i = threadIdx.x; i < N4; i += 256) {
        int c = g * 16 + (i >> 8);
        float gm = gamma[c] * rstd;
        float gb = beta[c] - mean * gm;
        float4 v = xp[i];
        py[i * 2]     = __float22half2_rn(make_float2(v.x * gm + gb, v.y * gm + gb));
        py[i * 2 + 1] = __float22half2_rn(make_float2(v.z * gm + gb, v.w * gm + gb));
    }
}

// ---------------- weight fp16 convert (both weights, one launch) ----------------
#define WQ4 (1536 * NC / 4)
#define WP4 (NC * NC / 4)
__global__ __launch_bounds__(256) void wconv_all(
    const float* __restrict__ wq, const float* __restrict__ wp,
    __half* __restrict__ wqh, __half* __restrict__ wph)
{
    int i = blockIdx.x * 256 + threadIdx.x;
    const float* w; __half* wh; int j;
    if (i < WQ4) { w = wq; wh = wqh; j = i; }
    else if (i < WQ4 + WP4) { w = wp; wh = wph; j = i - WQ4; }
    else return;
    float4 v = reinterpret_cast<const float4*>(w)[j];
    reinterpret_cast<__half2*>(wh)[j * 2]     = __float22half2_rn(make_float2(v.x, v.y));
    reinterpret_cast<__half2*>(wh)[j * 2 + 1] = __float22half2_rn(make_float2(v.z, v.w));
}

// ---------------- launch ----------------
extern "C" void kernel_launch(void* const* d_in, const int* in_sizes, int n_in,
                              void* d_out, int out_size)
{
    const float* x      = (const float*)d_in[0];
    const float* gamma  = (const float*)d_in[1];
    const float* beta   = (const float*)d_in[2];
    const float* qkv_w  = (const float*)d_in[3];
    const float* qkv_b  = (const float*)d_in[4];
    const float* proj_w = (const float*)d_in[5];
    const float* proj_b = (const float*)d_in[6];
    float* out = (float*)d_out;

    __half *qkv, *hin, *P, *H, *wq, *wp;
    cudaGetSymbolAddress((void**)&qkv, g_qkv);
    cudaGetSymbolAddress((void**)&hin, g_hin);
    cudaGetSymbolAddress((void**)&P,   g_P);
    cudaGetSymbolAddress((void**)&H,   g_H);
    cudaGetSymbolAddress((void**)&wq,  g_wq);
    cudaGetSymbolAddress((void**)&wp,  g_wp);

    cudaFuncSetAttribute(tc_gemm<0, false, true >, cudaFuncAttributeMaxDynamicSharedMemorySize, SMEMB);
    cudaFuncSetAttribute(tc_gemm<1, true,  true >, cudaFuncAttributeMaxDynamicSharedMemorySize, SMEMB);
    cudaFuncSetAttribute(tc_gemm<2, false, false>, cudaFuncAttributeMaxDynamicSharedMemorySize, SMEMB);
    cudaFuncSetAttribute(tc_gemm<3, false, true >, cudaFuncAttributeMaxDynamicSharedMemorySize, SMEMB);

    const long long s3  = 3LL * CHW;
    const long long sSS = (long long)NHW * NHW;
    const float attn_scale = 1.0f / sqrtf((float)NC);

    // 1) operand prep
    gn_all<<<NB * 32, 256>>>(x, gamma, beta, hin);
    wconv_all<<<(WQ4 + WP4 + 255) / 256, 256>>>(qkv_w, proj_w, wq, wp);

    // 2) QKV = W @ gn(x): M=1536, N=1024, K=512.  A direct, B trans
    tc_gemm<0, false, true><<<dim3(8, 12, NB), 256, SMEMB>>>(
        wq, 0LL, NC, hin, (long long)CHW, NHW, NC,
        nullptr, qkv, s3, qkv_b, nullptr, 1.0f);

    // 3) S = softmax32(alpha * Q^T K): M=N=1024, K=512. Both trans
    tc_gemm<1, true, true><<<dim3(8, 8, NB), 256, SMEMB>>>(
        qkv, s3, NHW, qkv + CHW, s3, NHW, NC,
        nullptr, P, sSS, nullptr, nullptr, attn_scale);

    // 4) H[c][p] = sum_q V[c][q] P[p][q]: M=512, N=1024, K=1024. Both direct
    tc_gemm<2, false, false><<<dim3(8, 4, NB), 256, SMEMB>>>(
        qkv + 2LL * CHW, s3, NHW, P, sSS, NHW, NHW,
        nullptr, H, (long long)CHW, nullptr, nullptr, 1.0f);

    // 5) out = x + proj_w @ H + proj_b: M=512, N=1024, K=512. A direct, B trans
    tc_gemm<3, false, true><<<dim3(8, 4, NB), 256, SMEMB>>>(
        wp, 0LL, NC, H, (long long)CHW, NHW, NC,
        out, nullptr, (long long)CHW, proj_b, x, 1.0f);
}